// round 1
// baseline (speedup 1.0000x reference)
#include <cuda_runtime.h>
#include <cstdint>

#define BATCH 8192
#define NV    1000
#define CHEBK 5
#define NF    5
#define HIDD  256
#define NOUT  10
#define POOLD 625
#define MAXW  96
#define BT    8

// ---------------- scratch (no allocation allowed -> __device__ globals) ----------------
__device__ float g_ell_val[NV * MAXW];
__device__ int   g_ell_col[NV * MAXW];
__device__ int   g_ell_len[NV];
__device__ float g_pool[(size_t)BATCH * POOLD];   // after cheby+cl1+relu+pool
__device__ float g_z1[(size_t)BATCH * HIDD];      // after fc1 + BN/JK
__device__ float g_z2[(size_t)BATCH * HIDD];      // after lin1 + relu

// ---------------- kernel 1: build ELL of Lr = 2*L/lmax - I ----------------
// One thread per row v. L is symmetric, so read column v (coalesced across threads).
// Sequential scan -> deterministic, column-sorted entries.
__global__ void build_ell(const float* __restrict__ L, const float* __restrict__ lmax) {
    const int v = blockIdx.x * blockDim.x + threadIdx.x;
    if (v >= NV) return;
    const float inv = 2.0f / lmax[0];
    int cnt = 0;
    for (int u = 0; u < NV; ++u) {
        float val = L[(size_t)u * NV + v] * inv - (u == v ? 1.0f : 0.0f);
        if (val != 0.0f) {
            if (cnt < MAXW) {
                g_ell_col[v * MAXW + cnt] = u;
                g_ell_val[v * MAXW + cnt] = val;
            }
            ++cnt;
        }
    }
    g_ell_len[v] = cnt < MAXW ? cnt : MAXW;
}

// ---------------- kernel 2: fused chebyshev recursion + cl1 + relu + maxpool(8) ----------
// One CTA handles BT=8 batch columns. All K=5 bases for all V nodes in smem:
// sT[k][v][bb], 5*1000*8*4 = 160000 bytes.
__global__ __launch_bounds__(512, 1)
void cheby_fused(const float* __restrict__ x,       // [B, V]
                 const float* __restrict__ W,       // cl1_W [5][5]
                 const float* __restrict__ bias) {  // cl1_b [5]
    extern __shared__ float sT[];                   // [CHEBK][NV][BT]
    const int b0  = blockIdx.x * BT;
    const int tid = threadIdx.x;
    const int nth = blockDim.x;

    // T0[v][bb] = x[b0+bb][v]
    #pragma unroll
    for (int bb = 0; bb < BT; ++bb) {
        const float* xr = x + (size_t)(b0 + bb) * NV;
        for (int v = tid; v < NV; v += nth) sT[v * BT + bb] = xr[v];
    }
    __syncthreads();

    // Recursion: T1 = Lr T0; Tk = 2 Lr T_{k-1} - T_{k-2}
    for (int k = 1; k < CHEBK; ++k) {
        float*       Tk  = sT + k * (NV * BT);
        const float* Tm1 = Tk - NV * BT;
        const float* Tm2 = Tk - 2 * NV * BT;   // unused when k==1
        for (int v = tid; v < NV; v += nth) {
            const int len = g_ell_len[v];
            const int*   __restrict__ cols = g_ell_col + v * MAXW;
            const float* __restrict__ vals = g_ell_val + v * MAXW;
            float acc[BT];
            #pragma unroll
            for (int bb = 0; bb < BT; ++bb) acc[bb] = 0.0f;
            for (int j = 0; j < len; ++j) {
                const float w = vals[j];
                const float4* Tr = reinterpret_cast<const float4*>(Tm1 + cols[j] * BT);
                const float4 t0 = Tr[0], t1 = Tr[1];
                acc[0] += w * t0.x; acc[1] += w * t0.y; acc[2] += w * t0.z; acc[3] += w * t0.w;
                acc[4] += w * t1.x; acc[5] += w * t1.y; acc[6] += w * t1.z; acc[7] += w * t1.w;
            }
            if (k == 1) {
                #pragma unroll
                for (int bb = 0; bb < BT; ++bb) Tk[v * BT + bb] = acc[bb];
            } else {
                #pragma unroll
                for (int bb = 0; bb < BT; ++bb) Tk[v * BT + bb] = 2.0f * acc[bb] - Tm2[v * BT + bb];
            }
        }
        __syncthreads();
    }

    // cl1 weights in registers
    float Wf[NF][CHEBK], bf[NF];
    #pragma unroll
    for (int f = 0; f < NF; ++f) {
        bf[f] = __ldg(bias + f);
        #pragma unroll
        for (int k = 0; k < CHEBK; ++k) Wf[f][k] = __ldg(W + f * CHEBK + k);
    }

    // h[b,v,f] = relu(sum_k Wf[f][k]*T_k[v,b] + bf[f]); pool = max over 8 nodes.
    // relu(max) == max(relu) since relu monotone.
    for (int i = tid; i < BT * 125; i += nth) {
        const int bb = i / 125;
        const int g  = i % 125;
        float m[NF];
        #pragma unroll
        for (int f = 0; f < NF; ++f) m[f] = -3.4e38f;
        #pragma unroll
        for (int vi = 0; vi < 8; ++vi) {
            const int v = g * 8 + vi;
            float t[CHEBK];
            #pragma unroll
            for (int k = 0; k < CHEBK; ++k) t[k] = sT[k * (NV * BT) + v * BT + bb];
            #pragma unroll
            for (int f = 0; f < NF; ++f) {
                float s = bf[f];
                #pragma unroll
                for (int k = 0; k < CHEBK; ++k) s += Wf[f][k] * t[k];
                m[f] = fmaxf(m[f], s);
            }
        }
        float* op = g_pool + (size_t)(b0 + bb) * POOLD + g * NF;
        #pragma unroll
        for (int f = 0; f < NF; ++f) op[f] = fmaxf(m[f], 0.0f);
    }
}

// ---------------- kernel 3/4: fp32 SGEMM  C = A @ B^T (+ fused epilogue) ----------------
// A: [M, Kd] row-major (K contiguous); Bw: [N, Kd] row-major (K contiguous).
// EPI=0: fc1 -> bias + 4x(BN, relu) chain + JK max.  EPI=1: lin1 -> bias + relu.
#define GBM 128
#define GBN 64
#define GBK 16
#define GTM 8
#define GTN 8
#define GPAD 17

template <int EPI>
__global__ __launch_bounds__(128, 2)
void gemm_nt(const float* __restrict__ A, const float* __restrict__ Bw,
             const float* __restrict__ bias,
             const float* __restrict__ bn_gamma, const float* __restrict__ bn_beta,
             const float* __restrict__ bn_mean,  const float* __restrict__ bn_var,
             float* __restrict__ C, int Kd, int N) {
    __shared__ float As[GBM * GPAD];
    __shared__ float Bs[GBN * GPAD];

    const int tid  = threadIdx.x;
    const int tx   = tid & 7;        // 0..7  -> 8 cols of 8
    const int ty   = tid >> 3;       // 0..15 -> 16 rows of 8
    const int row0 = blockIdx.y * GBM;
    const int col0 = blockIdx.x * GBN;

    float acc[GTM][GTN];
    #pragma unroll
    for (int i = 0; i < GTM; ++i)
        #pragma unroll
        for (int j = 0; j < GTN; ++j) acc[i][j] = 0.0f;

    for (int kt = 0; kt < Kd; kt += GBK) {
        #pragma unroll
        for (int e = tid; e < GBM * GBK; e += 128) {
            const int m = e >> 4, kk = e & 15;
            const int kg = kt + kk;
            As[m * GPAD + kk] = (kg < Kd) ? A[(size_t)(row0 + m) * Kd + kg] : 0.0f;
        }
        #pragma unroll
        for (int e = tid; e < GBN * GBK; e += 128) {
            const int n = e >> 4, kk = e & 15;
            const int kg = kt + kk;
            Bs[n * GPAD + kk] = (kg < Kd) ? Bw[(size_t)(col0 + n) * Kd + kg] : 0.0f;
        }
        __syncthreads();

        #pragma unroll
        for (int kk = 0; kk < GBK; ++kk) {
            float a[GTM], b[GTN];
            #pragma unroll
            for (int i = 0; i < GTM; ++i) a[i] = As[(ty * GTM + i) * GPAD + kk];
            #pragma unroll
            for (int j = 0; j < GTN; ++j) b[j] = Bs[(tx * GTN + j) * GPAD + kk];
            #pragma unroll
            for (int i = 0; i < GTM; ++i)
                #pragma unroll
                for (int j = 0; j < GTN; ++j) acc[i][j] += a[i] * b[j];
        }
        __syncthreads();
    }

    #pragma unroll
    for (int i = 0; i < GTM; ++i) {
        const int row = row0 + ty * GTM + i;
        #pragma unroll
        for (int j = 0; j < GTN; ++j) {
            const int col = col0 + tx * GTN + j;
            float y = acc[i][j] + __ldg(bias + col);
            if (EPI == 0) {
                float z = 0.0f;  // all JK candidates are relu'ed -> >= 0
                #pragma unroll
                for (int l = 0; l < 4; ++l) {
                    const int idx = l * HIDD + col;
                    const float sc = __ldg(bn_gamma + idx) * rsqrtf(__ldg(bn_var + idx) + 1e-5f);
                    y = (y - __ldg(bn_mean + idx)) * sc + __ldg(bn_beta + idx);
                    y = fmaxf(y, 0.0f);
                    z = fmaxf(z, y);
                }
                C[(size_t)row * N + col] = z;
            } else {
                C[(size_t)row * N + col] = fmaxf(y, 0.0f);
            }
        }
    }
}

// ---------------- kernel 5: lin2 (256 -> 10) + log_softmax, one warp per row ------------
__global__ void lin2_lsm(const float* __restrict__ Z2, const float* __restrict__ W2,
                         const float* __restrict__ b2, float* __restrict__ out) {
    const int gw   = (blockIdx.x * blockDim.x + threadIdx.x) >> 5;
    const int lane = threadIdx.x & 31;
    if (gw >= BATCH) return;
    const float* zr = Z2 + (size_t)gw * HIDD;
    float z[8];
    #pragma unroll
    for (int j = 0; j < 8; ++j) z[j] = zr[lane + 32 * j];

    float logit[NOUT];
    #pragma unroll
    for (int o = 0; o < NOUT; ++o) {
        float p = 0.0f;
        #pragma unroll
        for (int j = 0; j < 8; ++j) p += z[j] * __ldg(W2 + o * HIDD + lane + 32 * j);
        #pragma unroll
        for (int off = 16; off; off >>= 1) p += __shfl_xor_sync(0xffffffffu, p, off);
        logit[o] = p + __ldg(b2 + o);
    }
    float m = logit[0];
    #pragma unroll
    for (int o = 1; o < NOUT; ++o) m = fmaxf(m, logit[o]);
    float s = 0.0f;
    #pragma unroll
    for (int o = 0; o < NOUT; ++o) s += expf(logit[o] - m);
    const float lse = m + logf(s);
    if (lane < NOUT) out[(size_t)gw * NOUT + lane] = logit[lane] - lse;
}

// ---------------- launcher ----------------
extern "C" void kernel_launch(void* const* d_in, const int* in_sizes, int n_in,
                              void* d_out, int out_size) {
    const float* x        = (const float*)d_in[0];
    const float* L        = (const float*)d_in[1];
    const float* lmax     = (const float*)d_in[2];
    const float* cl1W     = (const float*)d_in[3];
    const float* cl1b     = (const float*)d_in[4];
    const float* fc1W     = (const float*)d_in[5];
    const float* fc1b     = (const float*)d_in[6];
    const float* bn_gamma = (const float*)d_in[7];
    const float* bn_beta  = (const float*)d_in[8];
    const float* bn_mean  = (const float*)d_in[9];
    const float* bn_var   = (const float*)d_in[10];
    const float* lin1W    = (const float*)d_in[11];
    const float* lin1b    = (const float*)d_in[12];
    const float* lin2W    = (const float*)d_in[13];
    const float* lin2b    = (const float*)d_in[14];
    float* out = (float*)d_out;

    float *pPool, *pZ1, *pZ2;
    cudaGetSymbolAddress((void**)&pPool, g_pool);
    cudaGetSymbolAddress((void**)&pZ1,  g_z1);
    cudaGetSymbolAddress((void**)&pZ2,  g_z2);

    // 1) sparse extraction of Lr
    build_ell<<<(NV + 255) / 256, 256>>>(L, lmax);

    // 2) fused chebyshev + cl1 + relu + maxpool
    const int smem = CHEBK * NV * BT * (int)sizeof(float);  // 160000 B
    cudaFuncSetAttribute(cheby_fused, cudaFuncAttributeMaxDynamicSharedMemorySize, smem);
    cheby_fused<<<BATCH / BT, 512, smem>>>(x, cl1W, cl1b);

    // 3) fc1 + BN x4 + relu + JK-max  (M=8192, N=256, K=625)
    dim3 grid(HIDD / GBN, BATCH / GBM);   // (4, 64)
    gemm_nt<0><<<grid, 128>>>(pPool, fc1W, fc1b, bn_gamma, bn_beta, bn_mean, bn_var,
                              pZ1, POOLD, HIDD);

    // 4) lin1 + relu  (M=8192, N=256, K=256)
    gemm_nt<1><<<grid, 128>>>(pZ1, lin1W, lin1b, nullptr, nullptr, nullptr, nullptr,
                              pZ2, HIDD, HIDD);

    // 5) lin2 + log_softmax
    lin2_lsm<<<BATCH / 8, 256>>>(pZ2, lin2W, lin2b, out);
}

// round 3
// speedup vs baseline: 1.6215x; 1.6215x over previous
#include <cuda_runtime.h>
#include <cstdint>

#define BATCH 8192
#define NV    1000
#define CHEBK 5
#define NF    5
#define HIDD  256
#define NOUT  10
#define POOLD 625
#define MAXW  32
#define BT    8

// ---------------- scratch ----------------
__device__ int2  g_ell[NV * MAXW];     // packed {col, __float_as_int(val)}
__device__ int   g_ell_len[NV];
__device__ float g_pool[(size_t)BATCH * POOLD];
__device__ float g_z1[(size_t)BATCH * HIDD];
__device__ float g_z2[(size_t)BATCH * HIDD];

// ---------------- kernel 1: build ELL of Lr = 2*L/lmax - I (warp/row, ballot compact) ----
// L is exactly symmetric (A+A^T with symmetric scaling), so row v == column v -> read
// row-major for coalescing. Ballot-prefix keeps entries column-sorted (deterministic).
__global__ void build_ell(const float* __restrict__ L, const float* __restrict__ lmax) {
    const int warp = (blockIdx.x * blockDim.x + threadIdx.x) >> 5;
    const int lane = threadIdx.x & 31;
    if (warp >= NV) return;
    const int v = warp;
    const float inv = 2.0f / lmax[0];
    int cnt = 0;
    #pragma unroll 4
    for (int c = 0; c < (NV + 31) / 32; ++c) {
        const int u = c * 32 + lane;
        float val = 0.0f;
        if (u < NV) val = L[(size_t)v * NV + u] * inv - (u == v ? 1.0f : 0.0f);
        const bool nz = (val != 0.0f);
        const unsigned m = __ballot_sync(0xffffffffu, nz);
        if (nz) {
            const int idx = cnt + __popc(m & ((1u << lane) - 1u));
            if (idx < MAXW) g_ell[v * MAXW + idx] = make_int2(u, __float_as_int(val));
        }
        cnt += __popc(m);
    }
    if (lane == 0) g_ell_len[v] = cnt < MAXW ? cnt : MAXW;
}

// ---------------- kernel 2: fused cheby + cl1 + relu + maxpool ----------------
// 1024 threads, one node per thread, BT=8 batch columns per CTA.
// smem: 5 planes sT[k][v][bb] = 160000 B.
__global__ __launch_bounds__(1024, 1)
void cheby_fused(const float* __restrict__ x,
                 const float* __restrict__ W,
                 const float* __restrict__ bias) {
    extern __shared__ float sT[];                 // [CHEBK][NV][BT]
    const int b0  = blockIdx.x * BT;
    const int tid = threadIdx.x;

    // T0[v][bb] = x[b0+bb][v]  (coalesced in v)
    #pragma unroll
    for (int i = tid; i < NV * BT; i += 1024) {
        const int bb = i / NV, v = i - bb * NV;
        sT[v * BT + bb] = x[(size_t)(b0 + bb) * NV + v];
    }
    __syncthreads();

    const int v = tid;
    int len = 0;
    const int2* __restrict__ ell = g_ell;
    if (v < NV) { len = g_ell_len[v]; ell = g_ell + v * MAXW; }

    #pragma unroll
    for (int k = 1; k < CHEBK; ++k) {
        const float* __restrict__ Tm1 = sT + (k - 1) * (NV * BT);
        float*       __restrict__ Tk  = sT + k * (NV * BT);
        if (v < NV) {
            float acc[BT];
            #pragma unroll
            for (int bb = 0; bb < BT; ++bb) acc[bb] = 0.0f;
            #pragma unroll 4
            for (int j = 0; j < len; ++j) {
                const int2 e = __ldg(&ell[j]);
                const float w = __int_as_float(e.y);
                const float4* tr = reinterpret_cast<const float4*>(Tm1 + e.x * BT);
                const float4 t0 = tr[0], t1 = tr[1];
                acc[0] += w * t0.x; acc[1] += w * t0.y; acc[2] += w * t0.z; acc[3] += w * t0.w;
                acc[4] += w * t1.x; acc[5] += w * t1.y; acc[6] += w * t1.z; acc[7] += w * t1.w;
            }
            float4* to = reinterpret_cast<float4*>(Tk + v * BT);
            if (k == 1) {
                to[0] = make_float4(acc[0], acc[1], acc[2], acc[3]);
                to[1] = make_float4(acc[4], acc[5], acc[6], acc[7]);
            } else {
                const float4* tm2 = reinterpret_cast<const float4*>(sT + (k - 2) * (NV * BT) + v * BT);
                const float4 m0 = tm2[0], m1 = tm2[1];
                to[0] = make_float4(2.0f * acc[0] - m0.x, 2.0f * acc[1] - m0.y,
                                    2.0f * acc[2] - m0.z, 2.0f * acc[3] - m0.w);
                to[1] = make_float4(2.0f * acc[4] - m1.x, 2.0f * acc[5] - m1.y,
                                    2.0f * acc[6] - m1.z, 2.0f * acc[7] - m1.w);
            }
        }
        __syncthreads();
    }

    if (tid < NV) {   // 1000 = 125 groups * 8 bb
        float Wf[NF][CHEBK], bf[NF];
        #pragma unroll
        for (int f = 0; f < NF; ++f) {
            bf[f] = __ldg(bias + f);
            #pragma unroll
            for (int k = 0; k < CHEBK; ++k) Wf[f][k] = __ldg(W + f * CHEBK + k);
        }
        const int bb = tid & 7;
        const int g  = tid >> 3;
        float m[NF];
        #pragma unroll
        for (int f = 0; f < NF; ++f) m[f] = -3.4e38f;
        #pragma unroll
        for (int vi = 0; vi < 8; ++vi) {
            const int vv = g * 8 + vi;
            float t[CHEBK];
            #pragma unroll
            for (int k = 0; k < CHEBK; ++k) t[k] = sT[k * (NV * BT) + vv * BT + bb];
            #pragma unroll
            for (int f = 0; f < NF; ++f) {
                float s = bf[f];
                #pragma unroll
                for (int k = 0; k < CHEBK; ++k) s += Wf[f][k] * t[k];
                m[f] = fmaxf(m[f], s);
            }
        }
        float* op = g_pool + (size_t)(b0 + bb) * POOLD + g * NF;
        #pragma unroll
        for (int f = 0; f < NF; ++f) op[f] = fmaxf(m[f], 0.0f);
    }
}

// ---------------- kernels 3/4: SGEMM C = A @ Bw^T + fused epilogue ----------------
#define BM 128
#define BN 128
#define BKg 16
#define SPAD 4
#define SAW (BM + SPAD)

template <int EPI>
__global__ __launch_bounds__(256, 2)
void gemm_nt(const float* __restrict__ A, const float* __restrict__ Bw,
             const float* __restrict__ bias,
             const float* __restrict__ bn_gamma, const float* __restrict__ bn_beta,
             const float* __restrict__ bn_mean,  const float* __restrict__ bn_var,
             float* __restrict__ C, int Kd, int N) {
    __shared__ float As[2][BKg][SAW];
    __shared__ float Bs[2][BKg][SAW];

    const int tid  = threadIdx.x;
    const int tx   = tid & 15;
    const int ty   = tid >> 4;
    const int row0 = blockIdx.y * BM;
    const int col0 = blockIdx.x * BN;

    float acc[8][8];
    #pragma unroll
    for (int i = 0; i < 8; ++i)
        #pragma unroll
        for (int j = 0; j < 8; ++j) acc[i][j] = 0.0f;

    const int ntiles = (Kd + BKg - 1) / BKg;

    // loader mapping: idx in [0,2048): m = idx>>4, kk = idx&15 (coalesced gmem)
    float ra[8], rb[8];
    auto load_tile = [&](int kt) {
        #pragma unroll
        for (int i = 0; i < 8; ++i) {
            const int idx = tid + i * 256;
            const int mm = idx >> 4, kk = idx & 15;
            const int kg = kt + kk;
            ra[i] = (kg < Kd) ? A[(size_t)(row0 + mm) * Kd + kg] : 0.0f;
            rb[i] = (kg < Kd) ? Bw[(size_t)(col0 + mm) * Kd + kg] : 0.0f;
        }
    };
    auto store_tile = [&](int p) {
        #pragma unroll
        for (int i = 0; i < 8; ++i) {
            const int idx = tid + i * 256;
            const int mm = idx >> 4, kk = idx & 15;
            As[p][kk][mm] = ra[i];
            Bs[p][kk][mm] = rb[i];
        }
    };

    load_tile(0);
    store_tile(0);
    __syncthreads();

    int p = 0;
    for (int t = 0; t < ntiles; ++t) {
        if (t + 1 < ntiles) load_tile((t + 1) * BKg);
        #pragma unroll
        for (int kk = 0; kk < BKg; ++kk) {
            float a[8], b[8];
            const float4* ap = reinterpret_cast<const float4*>(&As[p][kk][ty * 8]);
            const float4* bp = reinterpret_cast<const float4*>(&Bs[p][kk][tx * 8]);
            float4 a0 = ap[0], a1 = ap[1], b0 = bp[0], b1 = bp[1];
            a[0]=a0.x; a[1]=a0.y; a[2]=a0.z; a[3]=a0.w; a[4]=a1.x; a[5]=a1.y; a[6]=a1.z; a[7]=a1.w;
            b[0]=b0.x; b[1]=b0.y; b[2]=b0.z; b[3]=b0.w; b[4]=b1.x; b[5]=b1.y; b[6]=b1.z; b[7]=b1.w;
            #pragma unroll
            for (int i = 0; i < 8; ++i)
                #pragma unroll
                for (int j = 0; j < 8; ++j) acc[i][j] += a[i] * b[j];
        }
        if (t + 1 < ntiles) {
            __syncthreads();
            store_tile(p ^ 1);
            __syncthreads();
        }
        p ^= 1;
    }

    // per-column epilogue coefficients in registers
    float cb[8];
    float cs[8][4], ct[8][4];
    #pragma unroll
    for (int j = 0; j < 8; ++j) {
        const int col = col0 + tx * 8 + j;
        cb[j] = __ldg(bias + col);
        if (EPI == 0) {
            #pragma unroll
            for (int l = 0; l < 4; ++l) {
                const int idx = l * HIDD + col;
                const float s = __ldg(bn_gamma + idx) * rsqrtf(__ldg(bn_var + idx) + 1e-5f);
                cs[j][l] = s;
                ct[j][l] = __ldg(bn_beta + idx) - __ldg(bn_mean + idx) * s;
            }
        }
    }

    #pragma unroll
    for (int i = 0; i < 8; ++i) {
        const int row = row0 + ty * 8 + i;
        #pragma unroll
        for (int j = 0; j < 8; ++j) {
            const int col = col0 + tx * 8 + j;
            float y = acc[i][j] + cb[j];
            if (EPI == 0) {
                float z = 0.0f;
                #pragma unroll
                for (int l = 0; l < 4; ++l) {
                    y = fmaxf(y * cs[j][l] + ct[j][l], 0.0f);
                    z = fmaxf(z, y);
                }
                C[(size_t)row * N + col] = z;
            } else {
                C[(size_t)row * N + col] = fmaxf(y, 0.0f);
            }
        }
    }
}

// ---------------- kernel 5: lin2 + log_softmax ----------------
__global__ void lin2_lsm(const float* __restrict__ Z2, const float* __restrict__ W2,
                         const float* __restrict__ b2, float* __restrict__ out) {
    const int gw   = (blockIdx.x * blockDim.x + threadIdx.x) >> 5;
    const int lane = threadIdx.x & 31;
    if (gw >= BATCH) return;
    const float* zr = Z2 + (size_t)gw * HIDD;
    float z[8];
    #pragma unroll
    for (int j = 0; j < 8; ++j) z[j] = zr[lane + 32 * j];

    float logit[NOUT];
    #pragma unroll
    for (int o = 0; o < NOUT; ++o) {
        float p = 0.0f;
        #pragma unroll
        for (int j = 0; j < 8; ++j) p += z[j] * __ldg(W2 + o * HIDD + lane + 32 * j);
        #pragma unroll
        for (int off = 16; off; off >>= 1) p += __shfl_xor_sync(0xffffffffu, p, off);
        logit[o] = p + __ldg(b2 + o);
    }
    float m = logit[0];
    #pragma unroll
    for (int o = 1; o < NOUT; ++o) m = fmaxf(m, logit[o]);
    float s = 0.0f;
    #pragma unroll
    for (int o = 0; o < NOUT; ++o) s += expf(logit[o] - m);
    const float lse = m + logf(s);
    if (lane < NOUT) out[(size_t)gw * NOUT + lane] = logit[lane] - lse;
}

// ---------------- launcher ----------------
extern "C" void kernel_launch(void* const* d_in, const int* in_sizes, int n_in,
                              void* d_out, int out_size) {
    const float* x        = (const float*)d_in[0];
    const float* L        = (const float*)d_in[1];
    const float* lmax     = (const float*)d_in[2];
    const float* cl1W     = (const float*)d_in[3];
    const float* cl1b     = (const float*)d_in[4];
    const float* fc1W     = (const float*)d_in[5];
    const float* fc1b     = (const float*)d_in[6];
    const float* bn_gamma = (const float*)d_in[7];
    const float* bn_beta  = (const float*)d_in[8];
    const float* bn_mean  = (const float*)d_in[9];
    const float* bn_var   = (const float*)d_in[10];
    const float* lin1W    = (const float*)d_in[11];
    const float* lin1b    = (const float*)d_in[12];
    const float* lin2W    = (const float*)d_in[13];
    const float* lin2b    = (const float*)d_in[14];
    float* out = (float*)d_out;

    float *pPool, *pZ1, *pZ2;
    cudaGetSymbolAddress((void**)&pPool, g_pool);
    cudaGetSymbolAddress((void**)&pZ1,  g_z1);
    cudaGetSymbolAddress((void**)&pZ2,  g_z2);

    // 1) sparse extraction of Lr (warp per row)
    build_ell<<<(NV * 32 + 255) / 256, 256>>>(L, lmax);

    // 2) fused chebyshev + cl1 + relu + maxpool
    const int smem = CHEBK * NV * BT * (int)sizeof(float);  // 160000 B
    cudaFuncSetAttribute(cheby_fused, cudaFuncAttributeMaxDynamicSharedMemorySize, smem);
    cheby_fused<<<BATCH / BT, 1024, smem>>>(x, cl1W, cl1b);

    // 3) fc1 + BN x4 + relu + JK-max  (M=8192, N=256, K=625)
    dim3 grid(HIDD / BN, BATCH / BM);   // (2, 64)
    gemm_nt<0><<<grid, 256>>>(pPool, fc1W, fc1b, bn_gamma, bn_beta, bn_mean, bn_var,
                              pZ1, POOLD, HIDD);

    // 4) lin1 + relu  (M=8192, N=256, K=256)
    gemm_nt<1><<<grid, 256>>>(pZ1, lin1W, lin1b, nullptr, nullptr, nullptr, nullptr,
                              pZ2, HIDD, HIDD);

    // 5) lin2 + log_softmax
    lin2_lsm<<<BATCH / 8, 256>>>(pZ2, lin2W, lin2b, out);
}